// round 2
// baseline (speedup 1.0000x reference)
#include <cuda_runtime.h>
#include <mma.h>
using namespace nvcuda;

#define E_    32
#define KK    4
#define H_    1024
#define F_    1024
#define T_    1024
#define TWO_F 2048
#define NSLOT (T_*KK)   // 4096 total (token, k) slots

// ---------------- scratch (device globals; no allocation) ----------------
__device__ float g_t[T_*H_];          // rmsnormed tokens, 4MB
__device__ float g_topk_w[T_*KK];
__device__ int   g_topk_i[T_*KK];
__device__ int   g_cnt[E_];
__device__ int   g_off[E_];
__device__ int   g_tok[NSLOT];        // expert-grouped token ids
__device__ float g_sw[NSLOT];         // routing weight per slot
__device__ int   g_tslot[T_*KK];      // token -> its 4 slots
__device__ float g_act[(size_t)NSLOT*F_];   // 16MB, swiglu outputs
__device__ float g_comb[(size_t)NSLOT*H_];  // 16MB, per-slot mlp2 outputs

// ---------------- kernel 1: rmsnorm ----------------
__global__ void k_rmsnorm(const float* __restrict__ x, const float* __restrict__ scale) {
    int t = blockIdx.x;
    const float* xr = x + (size_t)t * H_;
    float s = 0.f;
    for (int h = threadIdx.x; h < H_; h += 256) { float v = xr[h]; s += v * v; }
    __shared__ float red[8];
    for (int o = 16; o; o >>= 1) s += __shfl_down_sync(0xffffffffu, s, o);
    if ((threadIdx.x & 31) == 0) red[threadIdx.x >> 5] = s;
    __syncthreads();
    if (threadIdx.x < 8) {
        s = red[threadIdx.x];
        for (int o = 4; o; o >>= 1) s += __shfl_down_sync(0xffu, s, o);
        if (threadIdx.x == 0) red[0] = rsqrtf(s / (float)H_ + 1e-5f);
    }
    __syncthreads();
    float r = red[0];
    for (int h = threadIdx.x; h < H_; h += 256)
        g_t[(size_t)t * H_ + h] = xr[h] * r * scale[h];
}

// ---------------- kernel 2: gate logits + top-4 softmax ----------------
__global__ void k_gate(const float* __restrict__ gw, const float* __restrict__ gb) {
    int t = blockIdx.x;
    int e = threadIdx.x >> 3, j = threadIdx.x & 7;   // 32 experts x 8 lanes
    const float* tr = g_t + (size_t)t * H_;
    const float* wr = gw + (size_t)e * H_;
    float s = 0.f;
    for (int h = j * 4; h < H_; h += 32) {
        s += tr[h] * wr[h] + tr[h+1] * wr[h+1] + tr[h+2] * wr[h+2] + tr[h+3] * wr[h+3];
    }
    for (int o = 4; o; o >>= 1) s += __shfl_down_sync(0xffffffffu, s, o);
    __shared__ float lg[E_];
    if (j == 0) lg[e] = s + gb[e];
    __syncthreads();
    if (threadIdx.x == 0) {
        float v[E_];
        #pragma unroll
        for (int i = 0; i < E_; i++) v[i] = lg[i];
        float tv[KK]; int ti[KK];
        for (int k = 0; k < KK; k++) {
            float best = -1e30f; int bi = 0;
            for (int i = 0; i < E_; i++) if (v[i] > best) { best = v[i]; bi = i; }
            tv[k] = best; ti[k] = bi; v[bi] = -1e30f;
        }
        float m = tv[0], den = 0.f, ex[KK];
        for (int k = 0; k < KK; k++) { ex[k] = expf(tv[k] - m); den += ex[k]; }
        for (int k = 0; k < KK; k++) {
            g_topk_w[t*KK + k] = ex[k] / den;
            g_topk_i[t*KK + k] = ti[k];
        }
    }
}

// ---------------- kernel 3: deterministic expert grouping ----------------
__global__ void k_build() {
    int e = threadIdx.x;   // 32 threads, one per expert
    const int4* idx4 = (const int4*)g_topk_i;
    int c = 0;
    for (int t = 0; t < T_; t++) {
        int4 q = idx4[t];
        c += (q.x == e) + (q.y == e) + (q.z == e) + (q.w == e);
    }
    g_cnt[e] = c;
    __syncthreads();
    if (e == 0) { int r = 0; for (int i = 0; i < E_; i++) { g_off[i] = r; r += g_cnt[i]; } }
    __syncthreads();
    int p = g_off[e];
    for (int t = 0; t < T_; t++) {
        int4 q = idx4[t];
        int id[4] = {q.x, q.y, q.z, q.w};
        #pragma unroll
        for (int k = 0; k < 4; k++) if (id[k] == e) {
            g_tok[p] = t;
            g_sw[p] = g_topk_w[t*KK + k];
            g_tslot[t*KK + k] = p;
            p++;
        }
    }
}

// ---------------- grouped GEMM tiles: BM=128, BN=64, BK=16, wmma tf32 ----------------
// smem union: double-buffered A/B tiles OR epilogue C tile
struct __align__(16) SMem {
    union {
        struct { float A[2][128][20]; float B[2][64][20]; } s;  // 30720 B
        float C[128][68];                                       // 34816 B
    };
};

__global__ void __launch_bounds__(256) k_mlp1(const float* __restrict__ w1,
                                              const float* __restrict__ b1) {
    int e = blockIdx.z;
    int cnt = g_cnt[e];
    int mtile = blockIdx.y;
    if (mtile * 128 >= cnt) return;
    int off = g_off[e];
    int ntile = blockIdx.x;            // 32 tiles over 2F
    int tid = threadIdx.x;

    __shared__ SMem sm;
    __shared__ int rowtok[128];
    if (tid < 128) {
        int m = mtile * 128 + tid;
        rowtok[tid] = (m < cnt) ? g_tok[off + m] : -1;
    }
    __syncthreads();

    const float* Bbase = w1 + ((size_t)e * TWO_F + (size_t)ntile * 64) * H_;

    wmma::fragment<wmma::accumulator, 16, 16, 8, float> acc[2][2];
    #pragma unroll
    for (int i = 0; i < 2; i++)
        #pragma unroll
        for (int j = 0; j < 2; j++) wmma::fill_fragment(acc[i][j], 0.f);

    int warpId = tid >> 5;
    int wm = warpId & 3, wn = warpId >> 2;   // 4x2 warp grid

    auto loadA = [&](int kt, float4* ra) {
        int k0 = kt * 16;
        #pragma unroll
        for (int i = 0; i < 2; i++) {
            int id = tid * 2 + i; int row = id >> 2, c4 = id & 3;
            int tok = rowtok[row];
            ra[i] = (tok >= 0) ? *(const float4*)(g_t + (size_t)tok * H_ + k0 + c4 * 4)
                               : make_float4(0.f, 0.f, 0.f, 0.f);
        }
    };
    auto loadB = [&](int kt, float4* rb) {
        int k0 = kt * 16;
        int row = tid >> 2, c4 = tid & 3;
        rb[0] = *(const float4*)(Bbase + (size_t)row * H_ + k0 + c4 * 4);
    };
    auto storeA = [&](int buf, float4* ra) {
        #pragma unroll
        for (int i = 0; i < 2; i++) {
            int id = tid * 2 + i; int row = id >> 2, c4 = id & 3;
            *(float4*)&sm.s.A[buf][row][c4 * 4] = ra[i];
        }
    };
    auto storeB = [&](int buf, float4* rb) {
        int row = tid >> 2, c4 = tid & 3;
        *(float4*)&sm.s.B[buf][row][c4 * 4] = rb[0];
    };

    float4 ra[2], rb[1];
    loadA(0, ra); loadB(0, rb);
    storeA(0, ra); storeB(0, rb);
    __syncthreads();

    const int NK = H_ / 16;   // 64
    for (int kt = 0; kt < NK; kt++) {
        int cur = kt & 1;
        if (kt + 1 < NK) { loadA(kt + 1, ra); loadB(kt + 1, rb); }
        #pragma unroll
        for (int ks = 0; ks < 2; ks++) {
            wmma::fragment<wmma::matrix_a, 16, 16, 8, wmma::precision::tf32, wmma::row_major> af[2];
            wmma::fragment<wmma::matrix_b, 16, 16, 8, wmma::precision::tf32, wmma::col_major> bf[2];
            #pragma unroll
            for (int i = 0; i < 2; i++) {
                wmma::load_matrix_sync(af[i], &sm.s.A[cur][wm * 32 + i * 16][ks * 8], 20);
                #pragma unroll
                for (int q = 0; q < af[i].num_elements; q++) af[i].x[q] = wmma::__float_to_tf32(af[i].x[q]);
            }
            #pragma unroll
            for (int j = 0; j < 2; j++) {
                wmma::load_matrix_sync(bf[j], &sm.s.B[cur][wn * 32 + j * 16][ks * 8], 20);
                #pragma unroll
                for (int q = 0; q < bf[j].num_elements; q++) bf[j].x[q] = wmma::__float_to_tf32(bf[j].x[q]);
            }
            #pragma unroll
            for (int i = 0; i < 2; i++)
                #pragma unroll
                for (int j = 0; j < 2; j++)
                    wmma::mma_sync(acc[i][j], af[i], bf[j], acc[i][j]);
        }
        if (kt + 1 < NK) { storeA(cur ^ 1, ra); storeB(cur ^ 1, rb); }
        __syncthreads();
    }

    // epilogue: C to smem, then fused interleaved swiglu -> g_act
    #pragma unroll
    for (int i = 0; i < 2; i++)
        #pragma unroll
        for (int j = 0; j < 2; j++)
            wmma::store_matrix_sync(&sm.C[wm * 32 + i * 16][wn * 32 + j * 16], acc[i][j], 68, wmma::mem_row_major);
    __syncthreads();

    int nvalid = min(128, cnt - mtile * 128);
    for (int p = tid; p < 128 * 32; p += 256) {
        int row = p >> 5, u = p & 31;
        if (row >= nvalid) continue;
        int j0 = ntile * 64 + 2 * u;
        float glu = sm.C[row][2 * u]     + b1[e * TWO_F + j0];
        float lin = sm.C[row][2 * u + 1] + b1[e * TWO_F + j0 + 1];
        glu = fminf(glu, 7.0f);
        lin = fminf(fmaxf(lin, -7.0f), 7.0f);
        float sig = 1.f / (1.f + __expf(-1.702f * glu));
        float a = glu * sig * (lin + 1.f);
        g_act[(size_t)(off + mtile * 128 + row) * F_ + ntile * 32 + u] = a;
    }
}

__global__ void __launch_bounds__(256) k_mlp2(const float* __restrict__ w2,
                                              const float* __restrict__ b2) {
    int e = blockIdx.z;
    int cnt = g_cnt[e];
    int mtile = blockIdx.y;
    if (mtile * 128 >= cnt) return;
    int off = g_off[e];
    int ntile = blockIdx.x;            // 16 tiles over H
    int tid = threadIdx.x;

    __shared__ SMem sm;

    const float* Bbase = w2 + ((size_t)e * H_ + (size_t)ntile * 64) * F_;

    wmma::fragment<wmma::accumulator, 16, 16, 8, float> acc[2][2];
    #pragma unroll
    for (int i = 0; i < 2; i++)
        #pragma unroll
        for (int j = 0; j < 2; j++) wmma::fill_fragment(acc[i][j], 0.f);

    int warpId = tid >> 5;
    int wm = warpId & 3, wn = warpId >> 2;

    auto loadA = [&](int kt, float4* ra) {
        int k0 = kt * 16;
        #pragma unroll
        for (int i = 0; i < 2; i++) {
            int id = tid * 2 + i; int row = id >> 2, c4 = id & 3;
            int m = mtile * 128 + row;
            ra[i] = (m < cnt) ? *(const float4*)(g_act + (size_t)(off + m) * F_ + k0 + c4 * 4)
                              : make_float4(0.f, 0.f, 0.f, 0.f);
        }
    };
    auto loadB = [&](int kt, float4* rb) {
        int k0 = kt * 16;
        int row = tid >> 2, c4 = tid & 3;
        rb[0] = *(const float4*)(Bbase + (size_t)row * F_ + k0 + c4 * 4);
    };
    auto storeA = [&](int buf, float4* ra) {
        #pragma unroll
        for (int i = 0; i < 2; i++) {
            int id = tid * 2 + i; int row = id >> 2, c4 = id & 3;
            *(float4*)&sm.s.A[buf][row][c4 * 4] = ra[i];
        }
    };
    auto storeB = [&](int buf, float4* rb) {
        int row = tid >> 2, c4 = tid & 3;
        *(float4*)&sm.s.B[buf][row][c4 * 4] = rb[0];
    };

    float4 ra[2], rb[1];
    loadA(0, ra); loadB(0, rb);
    storeA(0, ra); storeB(0, rb);
    __syncthreads();

    const int NK = F_ / 16;   // 64
    for (int kt = 0; kt < NK; kt++) {
        int cur = kt & 1;
        if (kt + 1 < NK) { loadA(kt + 1, ra); loadB(kt + 1, rb); }
        #pragma unroll
        for (int ks = 0; ks < 2; ks++) {
            wmma::fragment<wmma::matrix_a, 16, 16, 8, wmma::precision::tf32, wmma::row_major> af[2];
            wmma::fragment<wmma::matrix_b, 16, 16, 8, wmma::precision::tf32, wmma::col_major> bf[2];
            #pragma unroll
            for (int i = 0; i < 2; i++) {
                wmma::load_matrix_sync(af[i], &sm.s.A[cur][wm * 32 + i * 16][ks * 8], 20);
                #pragma unroll
                for (int q = 0; q < af[i].num_elements; q++) af[i].x[q] = wmma::__float_to_tf32(af[i].x[q]);
            }
            #pragma unroll
            for (int j = 0; j < 2; j++) {
                wmma::load_matrix_sync(bf[j], &sm.s.B[cur][wn * 32 + j * 16][ks * 8], 20);
                #pragma unroll
                for (int q = 0; q < bf[j].num_elements; q++) bf[j].x[q] = wmma::__float_to_tf32(bf[j].x[q]);
            }
            #pragma unroll
            for (int i = 0; i < 2; i++)
                #pragma unroll
                for (int j = 0; j < 2; j++)
                    wmma::mma_sync(acc[i][j], af[i], bf[j], acc[i][j]);
        }
        if (kt + 1 < NK) { storeA(cur ^ 1, ra); storeB(cur ^ 1, rb); }
        __syncthreads();
    }

    #pragma unroll
    for (int i = 0; i < 2; i++)
        #pragma unroll
        for (int j = 0; j < 2; j++)
            wmma::store_matrix_sync(&sm.C[wm * 32 + i * 16][wn * 32 + j * 16], acc[i][j], 68, wmma::mem_row_major);
    __syncthreads();

    int nvalid = min(128, cnt - mtile * 128);
    for (int p = tid; p < 128 * 64; p += 256) {
        int row = p >> 6, col = p & 63;
        if (row >= nvalid) continue;
        int n = ntile * 64 + col;
        int slot = off + mtile * 128 + row;
        float val = (sm.C[row][col] + b2[e * H_ + n]) * g_sw[slot];
        g_comb[(size_t)slot * H_ + n] = val;
    }
}

// ---------------- kernel 6: combine + residual ----------------
__global__ void k_combine(const float* __restrict__ x, float* __restrict__ out) {
    int t = blockIdx.x;
    int s0 = g_tslot[t * KK + 0];
    int s1 = g_tslot[t * KK + 1];
    int s2 = g_tslot[t * KK + 2];
    int s3 = g_tslot[t * KK + 3];
    for (int h = threadIdx.x; h < H_; h += 256) {
        out[(size_t)t * H_ + h] = x[(size_t)t * H_ + h]
            + g_comb[(size_t)s0 * H_ + h]
            + g_comb[(size_t)s1 * H_ + h]
            + g_comb[(size_t)s2 * H_ + h]
            + g_comb[(size_t)s3 * H_ + h];
    }
}

// ---------------- launch ----------------
extern "C" void kernel_launch(void* const* d_in, const int* in_sizes, int n_in,
                              void* d_out, int out_size) {
    const float* x  = (const float*)d_in[0];
    const float* ns = (const float*)d_in[1];
    const float* gw = (const float*)d_in[2];
    const float* gb = (const float*)d_in[3];
    const float* w1 = (const float*)d_in[4];
    const float* b1 = (const float*)d_in[5];
    const float* w2 = (const float*)d_in[6];
    const float* b2 = (const float*)d_in[7];
    float* out = (float*)d_out;

    k_rmsnorm<<<T_, 256>>>(x, ns);
    k_gate<<<T_, 256>>>(gw, gb);
    k_build<<<1, 32>>>();
    k_mlp1<<<dim3(32, 8, 32), 256>>>(w1, b1);
    k_mlp2<<<dim3(16, 8, 32), 256>>>(w2, b2);
    k_combine<<<T_, 256>>>(x, out);
}

// round 4
// speedup vs baseline: 1.0220x; 1.0220x over previous
#include <cuda_runtime.h>
#include <mma.h>
using namespace nvcuda;

#define E_    32
#define KK    4
#define H_    1024
#define F_    1024
#define T_    1024
#define TWO_F 2048
#define NSLOT (T_*KK)   // 4096 total (token, k) slots

// ---------------- scratch (device globals; no allocation) ----------------
__device__ float g_t[T_*H_];          // rmsnormed tokens, 4MB
__device__ float g_topk_w[T_*KK];
__device__ int   g_topk_i[T_*KK];
__device__ int   g_cnt[E_];
__device__ int   g_off[E_];
__device__ int   g_tok[NSLOT];        // expert-grouped token ids
__device__ float g_sw[NSLOT];         // routing weight per slot
__device__ int   g_tslot[T_*KK];      // token -> its 4 slots
__device__ float g_act[(size_t)NSLOT*F_];   // 16MB, swiglu outputs
__device__ float g_comb[(size_t)NSLOT*H_];  // 16MB, per-slot mlp2 outputs

// ---------------- kernel 1: rmsnorm ----------------
__global__ void k_rmsnorm(const float* __restrict__ x, const float* __restrict__ scale) {
    int t = blockIdx.x;
    const float* xr = x + (size_t)t * H_;
    float s = 0.f;
    for (int h = threadIdx.x; h < H_; h += 256) { float v = xr[h]; s += v * v; }
    __shared__ float red[8];
    for (int o = 16; o; o >>= 1) s += __shfl_down_sync(0xffffffffu, s, o);
    if ((threadIdx.x & 31) == 0) red[threadIdx.x >> 5] = s;
    __syncthreads();
    if (threadIdx.x < 8) {
        s = red[threadIdx.x];
        for (int o = 4; o; o >>= 1) s += __shfl_down_sync(0xffu, s, o);
        if (threadIdx.x == 0) red[0] = rsqrtf(s / (float)H_ + 1e-5f);
    }
    __syncthreads();
    float r = red[0];
    for (int h = threadIdx.x; h < H_; h += 256)
        g_t[(size_t)t * H_ + h] = xr[h] * r * scale[h];
}

// ---------------- kernel 2: gate logits + top-4 softmax ----------------
__global__ void k_gate(const float* __restrict__ gw, const float* __restrict__ gb) {
    int t = blockIdx.x;
    int e = threadIdx.x >> 3, j = threadIdx.x & 7;   // 32 experts x 8 lanes
    const float* tr = g_t + (size_t)t * H_;
    const float* wr = gw + (size_t)e * H_;
    float s = 0.f;
    for (int h = j * 4; h < H_; h += 32) {
        s += tr[h] * wr[h] + tr[h+1] * wr[h+1] + tr[h+2] * wr[h+2] + tr[h+3] * wr[h+3];
    }
    for (int o = 4; o; o >>= 1) s += __shfl_down_sync(0xffffffffu, s, o);
    __shared__ float lg[E_];
    if (j == 0) lg[e] = s + gb[e];
    __syncthreads();
    if (threadIdx.x == 0) {
        float v[E_];
        #pragma unroll
        for (int i = 0; i < E_; i++) v[i] = lg[i];
        float tv[KK]; int ti[KK];
        for (int k = 0; k < KK; k++) {
            float best = -1e30f; int bi = 0;
            for (int i = 0; i < E_; i++) if (v[i] > best) { best = v[i]; bi = i; }
            tv[k] = best; ti[k] = bi; v[bi] = -1e30f;
        }
        float m = tv[0], den = 0.f, ex[KK];
        for (int k = 0; k < KK; k++) { ex[k] = expf(tv[k] - m); den += ex[k]; }
        for (int k = 0; k < KK; k++) {
            g_topk_w[t*KK + k] = ex[k] / den;
            g_topk_i[t*KK + k] = ti[k];
        }
    }
}

// ---------------- kernel 3: deterministic expert grouping ----------------
__global__ void k_build() {
    int e = threadIdx.x;   // 32 threads, one per expert
    const int4* idx4 = (const int4*)g_topk_i;
    int c = 0;
    for (int t = 0; t < T_; t++) {
        int4 q = idx4[t];
        c += (q.x == e) + (q.y == e) + (q.z == e) + (q.w == e);
    }
    g_cnt[e] = c;
    __syncthreads();
    if (e == 0) { int r = 0; for (int i = 0; i < E_; i++) { g_off[i] = r; r += g_cnt[i]; } }
    __syncthreads();
    int p = g_off[e];
    for (int t = 0; t < T_; t++) {
        int4 q = idx4[t];
        int id[4] = {q.x, q.y, q.z, q.w};
        #pragma unroll
        for (int k = 0; k < 4; k++) if (id[k] == e) {
            g_tok[p] = t;
            g_sw[p] = g_topk_w[t*KK + k];
            g_tslot[t*KK + k] = p;
            p++;
        }
    }
}

// ---------------- grouped GEMM tiles: BM=128, BN=128, BK=16, wmma tf32 ----------------
// Data is rounded to tf32 ONCE at the gmem->smem store; fragments are used raw.
// smem union: double-buffered A/B tiles OR (half-width) epilogue C tile.
struct __align__(16) SMem {
    union {
        struct { float A[2][128][20]; float B[2][128][20]; } s;  // 40960 B
        float C[128][68];                                        // 34816 B
    };
};

__device__ __forceinline__ float4 cvt_tf32_f4(float4 v) {
    v.x = wmma::__float_to_tf32(v.x);
    v.y = wmma::__float_to_tf32(v.y);
    v.z = wmma::__float_to_tf32(v.z);
    v.w = wmma::__float_to_tf32(v.w);
    return v;
}

__global__ void __launch_bounds__(256, 2) k_mlp1(const float* __restrict__ w1,
                                                 const float* __restrict__ b1) {
    int e = blockIdx.z;
    int cnt = g_cnt[e];
    int mtile = blockIdx.y;
    if (mtile * 128 >= cnt) return;
    int off = g_off[e];
    int ntile = blockIdx.x;            // 16 tiles of 128 over 2F
    int tid = threadIdx.x;

    __shared__ SMem sm;
    __shared__ int rowtok[128];
    if (tid < 128) {
        int m = mtile * 128 + tid;
        rowtok[tid] = (m < cnt) ? g_tok[off + m] : -1;
    }
    __syncthreads();

    const float* Bbase = w1 + ((size_t)e * TWO_F + (size_t)ntile * 128) * H_;

    wmma::fragment<wmma::accumulator, 16, 16, 8, float> acc[2][4];
    #pragma unroll
    for (int i = 0; i < 2; i++)
        #pragma unroll
        for (int j = 0; j < 4; j++) wmma::fill_fragment(acc[i][j], 0.f);

    int warpId = tid >> 5;
    int wm = warpId & 3;       // M offset wm*32
    int wn = warpId >> 2;      // N offset wn*64

    // A tile: 128 rows x 16 K  (2048 floats -> 2 float4/thread)
    // B tile: 128 rows x 16 K  (2048 floats -> 2 float4/thread)
    auto loadA = [&](int kt, float4* ra) {
        int k0 = kt * 16;
        #pragma unroll
        for (int i = 0; i < 2; i++) {
            int id = tid * 2 + i; int row = id >> 2, c4 = id & 3;
            int tok = rowtok[row];
            ra[i] = (tok >= 0) ? *(const float4*)(g_t + (size_t)tok * H_ + k0 + c4 * 4)
                               : make_float4(0.f, 0.f, 0.f, 0.f);
        }
    };
    auto loadB = [&](int kt, float4* rb) {
        int k0 = kt * 16;
        #pragma unroll
        for (int i = 0; i < 2; i++) {
            int id = tid * 2 + i; int row = id >> 2, c4 = id & 3;
            rb[i] = *(const float4*)(Bbase + (size_t)row * H_ + k0 + c4 * 4);
        }
    };
    auto storeA = [&](int buf, float4* ra) {
        #pragma unroll
        for (int i = 0; i < 2; i++) {
            int id = tid * 2 + i; int row = id >> 2, c4 = id & 3;
            *(float4*)&sm.s.A[buf][row][c4 * 4] = cvt_tf32_f4(ra[i]);
        }
    };
    auto storeB = [&](int buf, float4* rb) {
        #pragma unroll
        for (int i = 0; i < 2; i++) {
            int id = tid * 2 + i; int row = id >> 2, c4 = id & 3;
            *(float4*)&sm.s.B[buf][row][c4 * 4] = cvt_tf32_f4(rb[i]);
        }
    };

    float4 ra[2], rb[2];
    loadA(0, ra); loadB(0, rb);
    storeA(0, ra); storeB(0, rb);
    __syncthreads();

    const int NK = H_ / 16;   // 64
    for (int kt = 0; kt < NK; kt++) {
        int cur = kt & 1;
        if (kt + 1 < NK) { loadA(kt + 1, ra); loadB(kt + 1, rb); }
        #pragma unroll
        for (int ks = 0; ks < 2; ks++) {
            wmma::fragment<wmma::matrix_a, 16, 16, 8, wmma::precision::tf32, wmma::row_major> af[2];
            wmma::fragment<wmma::matrix_b, 16, 16, 8, wmma::precision::tf32, wmma::col_major> bf[4];
            #pragma unroll
            for (int i = 0; i < 2; i++)
                wmma::load_matrix_sync(af[i], &sm.s.A[cur][wm * 32 + i * 16][ks * 8], 20);
            #pragma unroll
            for (int j = 0; j < 4; j++)
                wmma::load_matrix_sync(bf[j], &sm.s.B[cur][wn * 64 + j * 16][ks * 8], 20);
            #pragma unroll
            for (int i = 0; i < 2; i++)
                #pragma unroll
                for (int j = 0; j < 4; j++)
                    wmma::mma_sync(acc[i][j], af[i], bf[j], acc[i][j]);
        }
        if (kt + 1 < NK) { storeA(cur ^ 1, ra); storeB(cur ^ 1, rb); }
        __syncthreads();
    }

    // two-pass epilogue over the two 64-wide N halves; fused interleaved swiglu
    int nvalid = min(128, cnt - mtile * 128);
    #pragma unroll
    for (int half = 0; half < 2; half++) {
        if (half) __syncthreads();
        if (wn == half) {
            #pragma unroll
            for (int i = 0; i < 2; i++)
                #pragma unroll
                for (int j = 0; j < 4; j++)
                    wmma::store_matrix_sync(&sm.C[wm * 32 + i * 16][j * 16], acc[i][j], 68, wmma::mem_row_major);
        }
        __syncthreads();
        for (int p = tid; p < 128 * 32; p += 256) {
            int row = p >> 5, u = p & 31;
            if (row >= nvalid) continue;
            int j0 = ntile * 128 + half * 64 + 2 * u;
            float glu = sm.C[row][2 * u]     + b1[e * TWO_F + j0];
            float lin = sm.C[row][2 * u + 1] + b1[e * TWO_F + j0 + 1];
            glu = fminf(glu, 7.0f);
            lin = fminf(fmaxf(lin, -7.0f), 7.0f);
            float sig = 1.f / (1.f + __expf(-1.702f * glu));
            float a = glu * sig * (lin + 1.f);
            g_act[(size_t)(off + mtile * 128 + row) * F_ + ntile * 64 + half * 32 + u] = a;
        }
    }
}

__global__ void __launch_bounds__(256, 2) k_mlp2(const float* __restrict__ w2,
                                                 const float* __restrict__ b2) {
    int e = blockIdx.z;
    int cnt = g_cnt[e];
    int mtile = blockIdx.y;
    if (mtile * 128 >= cnt) return;
    int off = g_off[e];
    int ntile = blockIdx.x;            // 8 tiles of 128 over H
    int tid = threadIdx.x;

    __shared__ SMem sm;

    const float* Bbase = w2 + ((size_t)e * H_ + (size_t)ntile * 128) * F_;

    wmma::fragment<wmma::accumulator, 16, 16, 8, float> acc[2][4];
    #pragma unroll
    for (int i = 0; i < 2; i++)
        #pragma unroll
        for (int j = 0; j < 4; j++) wmma::fill_fragment(acc[i][j], 0.f);

    int warpId = tid >> 5;
    int wm = warpId & 3;
    int wn = warpId >> 2;

    auto loadA = [&](int kt, float4* ra) {
        int k0 = kt * 16;
        #pragma unroll
        for (int i = 0; i < 2; i++) {
            int id = tid * 2 + i; int row = id >> 2, c4 = id & 3;
            int m = mtile * 128 + row;
            ra[i] = (m < cnt) ? *(const float4*)(g_act + (size_t)(off + m) * F_ + k0 + c4 * 4)
                              : make_float4(0.f, 0.f, 0.f, 0.f);
        }
    };
    auto loadB = [&](int kt, float4* rb) {
        int k0 = kt * 16;
        #pragma unroll
        for (int i = 0; i < 2; i++) {
            int id = tid * 2 + i; int row = id >> 2, c4 = id & 3;
            rb[i] = *(const float4*)(Bbase + (size_t)row * F_ + k0 + c4 * 4);
        }
    };
    auto storeA = [&](int buf, float4* ra) {
        #pragma unroll
        for (int i = 0; i < 2; i++) {
            int id = tid * 2 + i; int row = id >> 2, c4 = id & 3;
            *(float4*)&sm.s.A[buf][row][c4 * 4] = cvt_tf32_f4(ra[i]);
        }
    };
    auto storeB = [&](int buf, float4* rb) {
        #pragma unroll
        for (int i = 0; i < 2; i++) {
            int id = tid * 2 + i; int row = id >> 2, c4 = id & 3;
            *(float4*)&sm.s.B[buf][row][c4 * 4] = cvt_tf32_f4(rb[i]);
        }
    };

    float4 ra[2], rb[2];
    loadA(0, ra); loadB(0, rb);
    storeA(0, ra); storeB(0, rb);
    __syncthreads();

    const int NK = F_ / 16;   // 64
    for (int kt = 0; kt < NK; kt++) {
        int cur = kt & 1;
        if (kt + 1 < NK) { loadA(kt + 1, ra); loadB(kt + 1, rb); }
        #pragma unroll
        for (int ks = 0; ks < 2; ks++) {
            wmma::fragment<wmma::matrix_a, 16, 16, 8, wmma::precision::tf32, wmma::row_major> af[2];
            wmma::fragment<wmma::matrix_b, 16, 16, 8, wmma::precision::tf32, wmma::col_major> bf[4];
            #pragma unroll
            for (int i = 0; i < 2; i++)
                wmma::load_matrix_sync(af[i], &sm.s.A[cur][wm * 32 + i * 16][ks * 8], 20);
            #pragma unroll
            for (int j = 0; j < 4; j++)
                wmma::load_matrix_sync(bf[j], &sm.s.B[cur][wn * 64 + j * 16][ks * 8], 20);
            #pragma unroll
            for (int i = 0; i < 2; i++)
                #pragma unroll
                for (int j = 0; j < 4; j++)
                    wmma::mma_sync(acc[i][j], af[i], bf[j], acc[i][j]);
        }
        if (kt + 1 < NK) { storeA(cur ^ 1, ra); storeB(cur ^ 1, rb); }
        __syncthreads();
    }

    int nvalid = min(128, cnt - mtile * 128);
    #pragma unroll
    for (int half = 0; half < 2; half++) {
        if (half) __syncthreads();
        if (wn == half) {
            #pragma unroll
            for (int i = 0; i < 2; i++)
                #pragma unroll
                for (int j = 0; j < 4; j++)
                    wmma::store_matrix_sync(&sm.C[wm * 32 + i * 16][j * 16], acc[i][j], 68, wmma::mem_row_major);
        }
        __syncthreads();
        for (int p = tid; p < 128 * 64; p += 256) {
            int row = p >> 6, col = p & 63;
            if (row >= nvalid) continue;
            int n = ntile * 128 + half * 64 + col;
            int slot = off + mtile * 128 + row;
            float val = (sm.C[row][col] + b2[e * H_ + n]) * g_sw[slot];
            g_comb[(size_t)slot * H_ + n] = val;
        }
    }
}

// ---------------- kernel 6: combine + residual ----------------
__global__ void k_combine(const float* __restrict__ x, float* __restrict__ out) {
    int t = blockIdx.x;
    int s0 = g_tslot[t * KK + 0];
    int s1 = g_tslot[t * KK + 1];
    int s2 = g_tslot[t * KK + 2];
    int s3 = g_tslot[t * KK + 3];
    for (int h = threadIdx.x; h < H_; h += 256) {
        out[(size_t)t * H_ + h] = x[(size_t)t * H_ + h]
            + g_comb[(size_t)s0 * H_ + h]
            + g_comb[(size_t)s1 * H_ + h]
            + g_comb[(size_t)s2 * H_ + h]
            + g_comb[(size_t)s3 * H_ + h];
    }
}

// ---------------- launch ----------------
extern "C" void kernel_launch(void* const* d_in, const int* in_sizes, int n_in,
                              void* d_out, int out_size) {
    const float* x  = (const float*)d_in[0];
    const float* ns = (const float*)d_in[1];
    const float* gw = (const float*)d_in[2];
    const float* gb = (const float*)d_in[3];
    const float* w1 = (const float*)d_in[4];
    const float* b1 = (const float*)d_in[5];
    const float* w2 = (const float*)d_in[6];
    const float* b2 = (const float*)d_in[7];
    float* out = (float*)d_out;

    k_rmsnorm<<<T_, 256>>>(x, ns);
    k_gate<<<T_, 256>>>(gw, gb);
    k_build<<<1, 32>>>();
    k_mlp1<<<dim3(16, 8, 32), 256>>>(w1, b1);
    k_mlp2<<<dim3(8, 8, 32), 256>>>(w2, b2);
    k_combine<<<T_, 256>>>(x, out);
}

// round 6
// speedup vs baseline: 1.7405x; 1.7031x over previous
#include <cuda_runtime.h>
#include <cstdint>

#define E_    32
#define KK    4
#define H_    1024
#define F_    1024
#define T_    1024
#define TWO_F 2048
#define NSLOT (T_*KK)

// ---------------- scratch (device globals; no allocation) ----------------
__device__ float g_t[T_*H_];
__device__ float g_topk_w[T_*KK];
__device__ int   g_topk_i[T_*KK];
__device__ int   g_cnt[E_];
__device__ int   g_off[E_];
__device__ int   g_tok[NSLOT];
__device__ float g_sw[NSLOT];
__device__ int   g_tslot[T_*KK];
__device__ float g_act[(size_t)NSLOT*F_];
__device__ float g_comb[(size_t)NSLOT*H_];

// ---------------- helpers ----------------
__device__ __forceinline__ uint32_t smem_u32(const void* p) {
    uint32_t a;
    asm("{ .reg .u64 t; cvta.to.shared.u64 t, %1; cvt.u32.u64 %0, t; }" : "=r"(a) : "l"(p));
    return a;
}

#define CPA16(dst, src, sz) \
    asm volatile("cp.async.ca.shared.global [%0], [%1], 16, %2;" \
        :: "r"(dst), "l"(src), "r"(sz))

#define CPA_COMMIT() asm volatile("cp.async.commit_group;")
#define CPA_WAIT1()  asm volatile("cp.async.wait_group 1;")
#define CPA_WAIT0()  asm volatile("cp.async.wait_group 0;")

#define LDMX4(r, addr) \
    asm volatile("ldmatrix.sync.aligned.m8n8.x4.shared.b16 {%0,%1,%2,%3}, [%4];" \
        : "=r"((r)[0]), "=r"((r)[1]), "=r"((r)[2]), "=r"((r)[3]) : "r"(addr))

#define MMA8(d, a, b0, b1) \
    asm volatile("mma.sync.aligned.m16n8k8.row.col.f32.tf32.tf32.f32 " \
        "{%0,%1,%2,%3}, {%4,%5,%6,%7}, {%8,%9}, {%0,%1,%2,%3};" \
        : "+f"((d)[0]), "+f"((d)[1]), "+f"((d)[2]), "+f"((d)[3]) \
        : "r"((a)[0]), "r"((a)[1]), "r"((a)[2]), "r"((a)[3]), "r"(b0), "r"(b1))

// dynamic smem: [0,512) rowtok; stages at 1024: stage s -> A (16KB) + B (16KB)
#define SM_STAGE0  1024
#define STAGE_B    32768
#define SMEM_MLP   (SM_STAGE0 + 3 * STAGE_B)   // 99328 B

// ---------------- kernel 1: rmsnorm ----------------
__global__ void k_rmsnorm(const float* __restrict__ x, const float* __restrict__ scale) {
    int t = blockIdx.x;
    const float* xr = x + (size_t)t * H_;
    float s = 0.f;
    for (int h = threadIdx.x; h < H_; h += 256) { float v = xr[h]; s += v * v; }
    __shared__ float red[8];
    for (int o = 16; o; o >>= 1) s += __shfl_down_sync(0xffffffffu, s, o);
    if ((threadIdx.x & 31) == 0) red[threadIdx.x >> 5] = s;
    __syncthreads();
    if (threadIdx.x < 8) {
        s = red[threadIdx.x];
        for (int o = 4; o; o >>= 1) s += __shfl_down_sync(0xffu, s, o);
        if (threadIdx.x == 0) red[0] = rsqrtf(s / (float)H_ + 1e-5f);
    }
    __syncthreads();
    float r = red[0];
    for (int h = threadIdx.x; h < H_; h += 256)
        g_t[(size_t)t * H_ + h] = xr[h] * r * scale[h];
}

// ---------------- kernel 2: gate + top-4 softmax ----------------
__global__ void k_gate(const float* __restrict__ gw, const float* __restrict__ gb) {
    int t = blockIdx.x;
    int e = threadIdx.x >> 3, j = threadIdx.x & 7;
    const float* tr = g_t + (size_t)t * H_;
    const float* wr = gw + (size_t)e * H_;
    float s = 0.f;
    for (int h = j * 4; h < H_; h += 32)
        s += tr[h]*wr[h] + tr[h+1]*wr[h+1] + tr[h+2]*wr[h+2] + tr[h+3]*wr[h+3];
    for (int o = 4; o; o >>= 1) s += __shfl_down_sync(0xffffffffu, s, o);
    __shared__ float lg[E_];
    if (j == 0) lg[e] = s + gb[e];
    __syncthreads();
    if (threadIdx.x == 0) {
        float v[E_];
        #pragma unroll
        for (int i = 0; i < E_; i++) v[i] = lg[i];
        float tv[KK]; int ti[KK];
        for (int k = 0; k < KK; k++) {
            float best = -1e30f; int bi = 0;
            for (int i = 0; i < E_; i++) if (v[i] > best) { best = v[i]; bi = i; }
            tv[k] = best; ti[k] = bi; v[bi] = -1e30f;
        }
        float m = tv[0], den = 0.f, ex[KK];
        for (int k = 0; k < KK; k++) { ex[k] = expf(tv[k] - m); den += ex[k]; }
        for (int k = 0; k < KK; k++) {
            g_topk_w[t*KK + k] = ex[k] / den;
            g_topk_i[t*KK + k] = ti[k];
        }
    }
}

// ---------------- kernel 3: deterministic grouping ----------------
__global__ void k_build() {
    int e = threadIdx.x;
    const int4* idx4 = (const int4*)g_topk_i;
    int c = 0;
    for (int t = 0; t < T_; t++) {
        int4 q = idx4[t];
        c += (q.x == e) + (q.y == e) + (q.z == e) + (q.w == e);
    }
    g_cnt[e] = c;
    __syncthreads();
    if (e == 0) { int r = 0; for (int i = 0; i < E_; i++) { g_off[i] = r; r += g_cnt[i]; } }
    __syncthreads();
    int p = g_off[e];
    for (int t = 0; t < T_; t++) {
        int4 q = idx4[t];
        int id[4] = {q.x, q.y, q.z, q.w};
        #pragma unroll
        for (int k = 0; k < 4; k++) if (id[k] == e) {
            g_tok[p] = t;
            g_sw[p] = g_topk_w[t*KK + k];
            g_tslot[t*KK + k] = p;
            p++;
        }
    }
}

// =====================================================================
// grouped GEMM: BM=128, BN=128, BK=32, mma.sync m16n8k8 tf32,
// ldmatrix.x4.b16 fragment loads on XOR-swizzled K-major tiles,
// 3-stage cp.async pipeline, reg->gmem fused epilogue.
// 8 warps as 4(M)x2(N): warp tile 32 x 64.
// =====================================================================

__device__ __forceinline__ float swiglu(float glu, float lin) {
    glu = fminf(glu, 7.0f);
    lin = fminf(fmaxf(lin, -7.0f), 7.0f);
    float sig = 1.f / (1.f + __expf(-1.702f * glu));
    return glu * sig * (lin + 1.f);
}

__global__ void __launch_bounds__(256, 2)
k_mlp1(const float* __restrict__ w1, const float* __restrict__ b1) {
    extern __shared__ char smem[];
    int e = blockIdx.z, mtile = blockIdx.y, ntile = blockIdx.x;
    int cnt = g_cnt[e];
    if (mtile * 128 >= cnt) return;
    int off = g_off[e];
    int tid = threadIdx.x, wid = tid >> 5, lane = tid & 31;
    int wm = wid & 3, wn = wid >> 2;
    int grp = lane >> 3, rin = lane & 7;
    uint32_t sb = smem_u32(smem);

    int* rowtok = (int*)smem;
    if (tid < 128) {
        int m = mtile * 128 + tid;
        rowtok[tid] = (m < cnt) ? g_tok[off + m] : -1;
    }
    __syncthreads();

    const float* Bb = w1 + ((size_t)e * TWO_F + (size_t)ntile * 128) * H_;

    int frow = tid >> 3, fc = tid & 7;                 // fill: 32 rows per i-step
    uint32_t fswz = (uint32_t)((fc ^ (frow & 7)) * 16);

    auto issue = [&](int kt) {
        int s = kt - (kt / 3) * 3;
        int k0 = kt * 32;
        uint32_t Ab = sb + SM_STAGE0 + s * STAGE_B;
        uint32_t Bbuf = Ab + 16384;
        #pragma unroll
        for (int i = 0; i < 4; i++) {
            int row = frow + i * 32;
            int tok = rowtok[row];
            const float* src = g_t + (size_t)(tok < 0 ? 0 : tok) * H_ + k0 + fc * 4;
            int sz = (tok >= 0) ? 16 : 0;
            CPA16(Ab + row * 128 + fswz, src, sz);
        }
        #pragma unroll
        for (int i = 0; i < 4; i++) {
            int row = frow + i * 32;
            const float* src = Bb + (size_t)row * H_ + k0 + fc * 4;
            CPA16(Bbuf + row * 128 + fswz, src, 16);
        }
        CPA_COMMIT();
    };

    float acc[2][8][4];
    #pragma unroll
    for (int mi = 0; mi < 2; mi++)
        #pragma unroll
        for (int ni = 0; ni < 8; ni++)
            #pragma unroll
            for (int q = 0; q < 4; q++) acc[mi][ni][q] = 0.f;

    issue(0); issue(1);

    uint32_t aOff = (uint32_t)((wm * 32 + (grp & 1) * 8 + rin) * 128);
    uint32_t bOff = (uint32_t)((wn * 64 + (grp >> 1) * 8 + rin) * 128);
    int caH = grp >> 1, cbH = grp & 1;

    for (int kt = 0; kt < 32; kt++) {
        int s = kt - (kt / 3) * 3;
        if (kt < 30) { CPA_WAIT1(); } else { CPA_WAIT0(); }
        __syncthreads();
        if (kt + 2 < 32) issue(kt + 2);

        uint32_t Ab = sb + SM_STAGE0 + s * STAGE_B;
        uint32_t Bbuf = Ab + 16384;
        uint32_t aBase = Ab + aOff;
        uint32_t bBase = Bbuf + bOff;

        #pragma unroll
        for (int ks = 0; ks < 4; ks++) {
            uint32_t a[2][4], b[4][4];
            uint32_t ca = (uint32_t)(((2 * ks + caH) ^ rin) * 16);
            uint32_t cb = (uint32_t)(((2 * ks + cbH) ^ rin) * 16);
            LDMX4(a[0], aBase + ca);
            LDMX4(a[1], aBase + 2048 + ca);
            #pragma unroll
            for (int j = 0; j < 4; j++) LDMX4(b[j], bBase + j * 2048 + cb);
            #pragma unroll
            for (int mi = 0; mi < 2; mi++)
                #pragma unroll
                for (int j = 0; j < 4; j++) {
                    MMA8(acc[mi][2*j],     a[mi], b[j][0], b[j][1]);
                    MMA8(acc[mi][2*j + 1], a[mi], b[j][2], b[j][3]);
                }
        }
    }

    // fused epilogue: bias + interleaved swiglu, regs -> g_act
    int nv = min(128, cnt - mtile * 128);
    int q = lane & 3, rr = lane >> 2;
    const float* b1p = b1 + (size_t)e * TWO_F + ntile * 128 + wn * 64;
    int acol0 = ntile * 64 + wn * 32;
    int mrowbase = off + mtile * 128;
    #pragma unroll
    for (int mi = 0; mi < 2; mi++) {
        int r1 = wm * 32 + mi * 16 + rr;
        #pragma unroll
        for (int ni = 0; ni < 8; ni++) {
            float be = __ldg(b1p + ni * 8 + 2 * q);
            float bo = __ldg(b1p + ni * 8 + 2 * q + 1);
            int ac = acol0 + ni * 4 + q;
            if (r1 < nv)
                g_act[(size_t)(mrowbase + r1) * F_ + ac] =
                    swiglu(acc[mi][ni][0] + be, acc[mi][ni][1] + bo);
            if (r1 + 8 < nv)
                g_act[(size_t)(mrowbase + r1 + 8) * F_ + ac] =
                    swiglu(acc[mi][ni][2] + be, acc[mi][ni][3] + bo);
        }
    }
}

__global__ void __launch_bounds__(256, 2)
k_mlp2(const float* __restrict__ w2, const float* __restrict__ b2) {
    extern __shared__ char smem[];
    int e = blockIdx.z, mtile = blockIdx.y, ntile = blockIdx.x;
    int cnt = g_cnt[e];
    if (mtile * 128 >= cnt) return;
    int off = g_off[e];
    int tid = threadIdx.x, wid = tid >> 5, lane = tid & 31;
    int wm = wid & 3, wn = wid >> 2;
    int grp = lane >> 3, rin = lane & 7;
    uint32_t sb = smem_u32(smem);

    const float* Bb = w2 + ((size_t)e * H_ + (size_t)ntile * 128) * F_;

    int frow = tid >> 3, fc = tid & 7;
    uint32_t fswz = (uint32_t)((fc ^ (frow & 7)) * 16);

    auto issue = [&](int kt) {
        int s = kt - (kt / 3) * 3;
        int k0 = kt * 32;
        uint32_t Ab = sb + SM_STAGE0 + s * STAGE_B;
        uint32_t Bbuf = Ab + 16384;
        #pragma unroll
        for (int i = 0; i < 4; i++) {
            int row = frow + i * 32;
            int m = mtile * 128 + row;
            int mc = min(m, cnt - 1);
            const float* src = g_act + (size_t)(off + mc) * F_ + k0 + fc * 4;
            int sz = (m < cnt) ? 16 : 0;
            CPA16(Ab + row * 128 + fswz, src, sz);
        }
        #pragma unroll
        for (int i = 0; i < 4; i++) {
            int row = frow + i * 32;
            const float* src = Bb + (size_t)row * F_ + k0 + fc * 4;
            CPA16(Bbuf + row * 128 + fswz, src, 16);
        }
        CPA_COMMIT();
    };

    float acc[2][8][4];
    #pragma unroll
    for (int mi = 0; mi < 2; mi++)
        #pragma unroll
        for (int ni = 0; ni < 8; ni++)
            #pragma unroll
            for (int q = 0; q < 4; q++) acc[mi][ni][q] = 0.f;

    issue(0); issue(1);

    uint32_t aOff = (uint32_t)((wm * 32 + (grp & 1) * 8 + rin) * 128);
    uint32_t bOff = (uint32_t)((wn * 64 + (grp >> 1) * 8 + rin) * 128);
    int caH = grp >> 1, cbH = grp & 1;

    for (int kt = 0; kt < 32; kt++) {
        int s = kt - (kt / 3) * 3;
        if (kt < 30) { CPA_WAIT1(); } else { CPA_WAIT0(); }
        __syncthreads();
        if (kt + 2 < 32) issue(kt + 2);

        uint32_t Ab = sb + SM_STAGE0 + s * STAGE_B;
        uint32_t Bbuf = Ab + 16384;
        uint32_t aBase = Ab + aOff;
        uint32_t bBase = Bbuf + bOff;

        #pragma unroll
        for (int ks = 0; ks < 4; ks++) {
            uint32_t a[2][4], b[4][4];
            uint32_t ca = (uint32_t)(((2 * ks + caH) ^ rin) * 16);
            uint32_t cb = (uint32_t)(((2 * ks + cbH) ^ rin) * 16);
            LDMX4(a[0], aBase + ca);
            LDMX4(a[1], aBase + 2048 + ca);
            #pragma unroll
            for (int j = 0; j < 4; j++) LDMX4(b[j], bBase + j * 2048 + cb);
            #pragma unroll
            for (int mi = 0; mi < 2; mi++)
                #pragma unroll
                for (int j = 0; j < 4; j++) {
                    MMA8(acc[mi][2*j],     a[mi], b[j][0], b[j][1]);
                    MMA8(acc[mi][2*j + 1], a[mi], b[j][2], b[j][3]);
                }
        }
    }

    // fused epilogue: (acc + b2) * routing weight -> g_comb
    int nv = min(128, cnt - mtile * 128);
    int q = lane & 3, rr = lane >> 2;
    const float* b2p = b2 + (size_t)e * H_ + ntile * 128 + wn * 64;
    int ocol0 = ntile * 128 + wn * 64;
    int slotbase = off + mtile * 128;
    #pragma unroll
    for (int mi = 0; mi < 2; mi++) {
        int r1 = wm * 32 + mi * 16 + rr;
        float sw1 = (r1 < nv)     ? g_sw[slotbase + r1]     : 0.f;
        float sw2 = (r1 + 8 < nv) ? g_sw[slotbase + r1 + 8] : 0.f;
        #pragma unroll
        for (int ni = 0; ni < 8; ni++) {
            int c0 = ni * 8 + 2 * q;
            float be = __ldg(b2p + c0);
            float bo = __ldg(b2p + c0 + 1);
            if (r1 < nv) {
                float2 v = make_float2((acc[mi][ni][0] + be) * sw1,
                                       (acc[mi][ni][1] + bo) * sw1);
                *(float2*)&g_comb[(size_t)(slotbase + r1) * H_ + ocol0 + c0] = v;
            }
            if (r1 + 8 < nv) {
                float2 v = make_float2((acc[mi][ni][2] + be) * sw2,
                                       (acc[mi][ni][3] + bo) * sw2);
                *(float2*)&g_comb[(size_t)(slotbase + r1 + 8) * H_ + ocol0 + c0] = v;
            }
        }
    }
}

// ---------------- kernel 6: combine + residual ----------------
__global__ void k_combine(const float* __restrict__ x, float* __restrict__ out) {
    int t = blockIdx.x;
    int s0 = g_tslot[t * KK + 0];
    int s1 = g_tslot[t * KK + 1];
    int s2 = g_tslot[t * KK + 2];
    int s3 = g_tslot[t * KK + 3];
    for (int h = threadIdx.x; h < H_; h += 256) {
        out[(size_t)t * H_ + h] = x[(size_t)t * H_ + h]
            + g_comb[(size_t)s0 * H_ + h]
            + g_comb[(size_t)s1 * H_ + h]
            + g_comb[(size_t)s2 * H_ + h]
            + g_comb[(size_t)s3 * H_ + h];
    }
}

// ---------------- launch ----------------
extern "C" void kernel_launch(void* const* d_in, const int* in_sizes, int n_in,
                              void* d_out, int out_size) {
    const float* x  = (const float*)d_in[0];
    const float* ns = (const float*)d_in[1];
    const float* gw = (const float*)d_in[2];
    const float* gb = (const float*)d_in[3];
    const float* w1 = (const float*)d_in[4];
    const float* b1 = (const float*)d_in[5];
    const float* w2 = (const float*)d_in[6];
    const float* b2 = (const float*)d_in[7];
    float* out = (float*)d_out;

    cudaFuncSetAttribute(k_mlp1, cudaFuncAttributeMaxDynamicSharedMemorySize, SMEM_MLP);
    cudaFuncSetAttribute(k_mlp2, cudaFuncAttributeMaxDynamicSharedMemorySize, SMEM_MLP);

    k_rmsnorm<<<T_, 256>>>(x, ns);
    k_gate<<<T_, 256>>>(gw, gb);
    k_build<<<1, 32>>>();
    k_mlp1<<<dim3(16, 8, 32), 256, SMEM_MLP>>>(w1, b1);
    k_mlp2<<<dim3(8, 8, 32), 256, SMEM_MLP>>>(w2, b2);
    k_combine<<<T_, 256>>>(x, out);
}

// round 7
// speedup vs baseline: 3.6354x; 2.0887x over previous
#include <cuda_runtime.h>
#include <cstdint>

#define E_    32
#define KK    4
#define H_    1024
#define F_    1024
#define T_    1024
#define TWO_F 2048
#define NSLOT (T_*KK)

// ---------------- scratch (device globals; no allocation) ----------------
__device__ float g_t[T_*H_];
__device__ float g_topk_w[T_*KK];
__device__ int   g_topk_i[T_*KK];
__device__ int   g_cnt[E_];
__device__ int   g_off[E_];
__device__ int   g_tok[NSLOT];
__device__ float g_sw[NSLOT];
__device__ int   g_tslot[T_*KK];
__device__ float g_act[(size_t)NSLOT*F_];
__device__ float g_comb[(size_t)NSLOT*H_];

// ---------------- helpers ----------------
__device__ __forceinline__ uint32_t smem_u32(const void* p) {
    uint32_t a;
    asm("{ .reg .u64 t; cvta.to.shared.u64 t, %1; cvt.u32.u64 %0, t; }" : "=r"(a) : "l"(p));
    return a;
}

#define CPA16(dst, src, sz) \
    asm volatile("cp.async.ca.shared.global [%0], [%1], 16, %2;" \
        :: "r"(dst), "l"(src), "r"(sz))

#define CPA_COMMIT() asm volatile("cp.async.commit_group;")
#define CPA_WAIT1()  asm volatile("cp.async.wait_group 1;")
#define CPA_WAIT0()  asm volatile("cp.async.wait_group 0;")

#define LDMX4(r, addr) \
    asm volatile("ldmatrix.sync.aligned.m8n8.x4.shared.b16 {%0,%1,%2,%3}, [%4];" \
        : "=r"((r)[0]), "=r"((r)[1]), "=r"((r)[2]), "=r"((r)[3]) : "r"(addr))

#define MMA8(d, a, b0, b1) \
    asm volatile("mma.sync.aligned.m16n8k8.row.col.f32.tf32.tf32.f32 " \
        "{%0,%1,%2,%3}, {%4,%5,%6,%7}, {%8,%9}, {%0,%1,%2,%3};" \
        : "+f"((d)[0]), "+f"((d)[1]), "+f"((d)[2]), "+f"((d)[3]) \
        : "r"((a)[0]), "r"((a)[1]), "r"((a)[2]), "r"((a)[3]), "r"(b0), "r"(b1))

// dynamic smem: [0,512) rowtok; stages at 1024: stage s -> A (16KB) + B (16KB)
#define SM_STAGE0  1024
#define STAGE_B    32768
#define SMEM_MLP   (SM_STAGE0 + 3 * STAGE_B)   // 99328 B

// ---------------- kernel 1: fused rmsnorm + gate + top-4 softmax ----------------
__global__ void __launch_bounds__(256) k_norm_gate(
    const float* __restrict__ x, const float* __restrict__ scale,
    const float* __restrict__ gw, const float* __restrict__ gb) {
    __shared__ float ts[H_];
    __shared__ float red[8];
    __shared__ float lg[E_];
    int t = blockIdx.x;
    const float* xr = x + (size_t)t * H_;
    float s = 0.f;
    float xv[4];
    #pragma unroll
    for (int i = 0; i < 4; i++) { xv[i] = xr[threadIdx.x + i * 256]; s += xv[i] * xv[i]; }
    for (int o = 16; o; o >>= 1) s += __shfl_down_sync(0xffffffffu, s, o);
    if ((threadIdx.x & 31) == 0) red[threadIdx.x >> 5] = s;
    __syncthreads();
    if (threadIdx.x < 8) {
        s = red[threadIdx.x];
        for (int o = 4; o; o >>= 1) s += __shfl_down_sync(0xffu, s, o);
        if (threadIdx.x == 0) red[0] = rsqrtf(s / (float)H_ + 1e-5f);
    }
    __syncthreads();
    float r = red[0];
    #pragma unroll
    for (int i = 0; i < 4; i++) {
        int h = threadIdx.x + i * 256;
        float v = xv[i] * r * scale[h];
        ts[h] = v;
        g_t[(size_t)t * H_ + h] = v;
    }
    __syncthreads();
    // gate: 32 experts x 8 lanes, reading normalized row from smem
    int e = threadIdx.x >> 3, j = threadIdx.x & 7;
    const float* wr = gw + (size_t)e * H_;
    float acc = 0.f;
    for (int h = j * 4; h < H_; h += 32)
        acc += ts[h]*wr[h] + ts[h+1]*wr[h+1] + ts[h+2]*wr[h+2] + ts[h+3]*wr[h+3];
    for (int o = 4; o; o >>= 1) acc += __shfl_down_sync(0xffffffffu, acc, o);
    if (j == 0) lg[e] = acc + gb[e];
    __syncthreads();
    if (threadIdx.x == 0) {
        float v[E_];
        #pragma unroll
        for (int i = 0; i < E_; i++) v[i] = lg[i];
        float tv[KK]; int ti[KK];
        for (int k = 0; k < KK; k++) {
            float best = -1e30f; int bi = 0;
            for (int i = 0; i < E_; i++) if (v[i] > best) { best = v[i]; bi = i; }
            tv[k] = best; ti[k] = bi; v[bi] = -1e30f;
        }
        float m = tv[0], den = 0.f, ex[KK];
        for (int k = 0; k < KK; k++) { ex[k] = expf(tv[k] - m); den += ex[k]; }
        for (int k = 0; k < KK; k++) {
            g_topk_w[t*KK + k] = ex[k] / den;
            g_topk_i[t*KK + k] = ti[k];
        }
    }
}

// ---------------- kernel 2: parallel deterministic grouping ----------------
// 1 block, 1024 threads (thread = token, 32 warps). Ordering identical to a
// serial token-major scan: per expert, tokens ascending (top-k experts are
// distinct within a token, so <=1 entry per token per expert).
__global__ void __launch_bounds__(1024) k_build() {
    __shared__ uint32_t wmask[32][E_];   // per-warp per-expert lane bitmask
    __shared__ int scanwe[32][E_];       // exclusive warp prefix per expert
    __shared__ int cnt_s[E_], off_s[E_];
    int t = threadIdx.x, w = t >> 5, lane = t & 31;

    ((uint32_t*)wmask)[t] = 0u;
    __syncthreads();

    int es[KK]; float ws[KK];
    #pragma unroll
    for (int j = 0; j < KK; j++) {
        es[j] = g_topk_i[t * KK + j];
        ws[j] = g_topk_w[t * KK + j];
        atomicOr(&wmask[w][es[j]], 1u << lane);
    }
    __syncthreads();

    if (t < E_) {                        // scan over 32 warps for expert t
        int run = 0;
        #pragma unroll
        for (int ww = 0; ww < 32; ww++) {
            scanwe[ww][t] = run;
            run += __popc(wmask[ww][t]);
        }
        cnt_s[t] = run;
        g_cnt[t] = run;
    }
    __syncthreads();
    if (t == 0) {
        int r = 0;
        #pragma unroll
        for (int i = 0; i < E_; i++) { off_s[i] = r; g_off[i] = r; r += cnt_s[i]; }
    }
    __syncthreads();

    uint32_t ltmask = (1u << lane) - 1u;
    #pragma unroll
    for (int j = 0; j < KK; j++) {
        int e = es[j];
        int p = off_s[e] + scanwe[w][e] + __popc(wmask[w][e] & ltmask);
        g_tok[p] = t;
        g_sw[p] = ws[j];
        g_tslot[t * KK + j] = p;
    }
}

// =====================================================================
// grouped GEMM: BM=128, BN=128, BK=32, mma.sync m16n8k8 tf32,
// ldmatrix.x4.b16 fragment loads on XOR-swizzled K-major tiles,
// 3-stage cp.async pipeline, reg->gmem fused epilogue.
// 8 warps as 4(M)x2(N): warp tile 32 x 64.
// =====================================================================

__device__ __forceinline__ float swiglu(float glu, float lin) {
    glu = fminf(glu, 7.0f);
    lin = fminf(fmaxf(lin, -7.0f), 7.0f);
    float sig = 1.f / (1.f + __expf(-1.702f * glu));
    return glu * sig * (lin + 1.f);
}

__global__ void __launch_bounds__(256, 2)
k_mlp1(const float* __restrict__ w1, const float* __restrict__ b1) {
    extern __shared__ char smem[];
    int e = blockIdx.z, mtile = blockIdx.y, ntile = blockIdx.x;
    int cnt = g_cnt[e];
    if (mtile * 128 >= cnt) return;
    int off = g_off[e];
    int tid = threadIdx.x, wid = tid >> 5, lane = tid & 31;
    int wm = wid & 3, wn = wid >> 2;
    int grp = lane >> 3, rin = lane & 7;
    uint32_t sb = smem_u32(smem);

    int* rowtok = (int*)smem;
    if (tid < 128) {
        int m = mtile * 128 + tid;
        rowtok[tid] = (m < cnt) ? g_tok[off + m] : -1;
    }
    __syncthreads();

    const float* Bb = w1 + ((size_t)e * TWO_F + (size_t)ntile * 128) * H_;

    int frow = tid >> 3, fc = tid & 7;
    uint32_t fswz = (uint32_t)((fc ^ (frow & 7)) * 16);

    auto issue = [&](int kt) {
        int s = kt - (kt / 3) * 3;
        int k0 = kt * 32;
        uint32_t Ab = sb + SM_STAGE0 + s * STAGE_B;
        uint32_t Bbuf = Ab + 16384;
        #pragma unroll
        for (int i = 0; i < 4; i++) {
            int row = frow + i * 32;
            int tok = rowtok[row];
            const float* src = g_t + (size_t)(tok < 0 ? 0 : tok) * H_ + k0 + fc * 4;
            int sz = (tok >= 0) ? 16 : 0;
            CPA16(Ab + row * 128 + fswz, src, sz);
        }
        #pragma unroll
        for (int i = 0; i < 4; i++) {
            int row = frow + i * 32;
            const float* src = Bb + (size_t)row * H_ + k0 + fc * 4;
            CPA16(Bbuf + row * 128 + fswz, src, 16);
        }
        CPA_COMMIT();
    };

    float acc[2][8][4];
    #pragma unroll
    for (int mi = 0; mi < 2; mi++)
        #pragma unroll
        for (int ni = 0; ni < 8; ni++)
            #pragma unroll
            for (int q = 0; q < 4; q++) acc[mi][ni][q] = 0.f;

    issue(0); issue(1);

    uint32_t aOff = (uint32_t)((wm * 32 + (grp & 1) * 8 + rin) * 128);
    uint32_t bOff = (uint32_t)((wn * 64 + (grp >> 1) * 8 + rin) * 128);
    int caH = grp >> 1, cbH = grp & 1;

    for (int kt = 0; kt < 32; kt++) {
        int s = kt - (kt / 3) * 3;
        if (kt < 30) { CPA_WAIT1(); } else { CPA_WAIT0(); }
        __syncthreads();
        if (kt + 2 < 32) issue(kt + 2);

        uint32_t Ab = sb + SM_STAGE0 + s * STAGE_B;
        uint32_t Bbuf = Ab + 16384;
        uint32_t aBase = Ab + aOff;
        uint32_t bBase = Bbuf + bOff;

        #pragma unroll
        for (int ks = 0; ks < 4; ks++) {
            uint32_t a[2][4], b[4][4];
            uint32_t ca = (uint32_t)(((2 * ks + caH) ^ rin) * 16);
            uint32_t cb = (uint32_t)(((2 * ks + cbH) ^ rin) * 16);
            LDMX4(a[0], aBase + ca);
            LDMX4(a[1], aBase + 2048 + ca);
            #pragma unroll
            for (int j = 0; j < 4; j++) LDMX4(b[j], bBase + j * 2048 + cb);
            #pragma unroll
            for (int mi = 0; mi < 2; mi++)
                #pragma unroll
                for (int j = 0; j < 4; j++) {
                    MMA8(acc[mi][2*j],     a[mi], b[j][0], b[j][1]);
                    MMA8(acc[mi][2*j + 1], a[mi], b[j][2], b[j][3]);
                }
        }
    }

    // fused epilogue: bias + interleaved swiglu, regs -> g_act
    int nv = min(128, cnt - mtile * 128);
    int q = lane & 3, rr = lane >> 2;
    const float* b1p = b1 + (size_t)e * TWO_F + ntile * 128 + wn * 64;
    int acol0 = ntile * 64 + wn * 32;
    int mrowbase = off + mtile * 128;
    #pragma unroll
    for (int mi = 0; mi < 2; mi++) {
        int r1 = wm * 32 + mi * 16 + rr;
        #pragma unroll
        for (int ni = 0; ni < 8; ni++) {
            float be = __ldg(b1p + ni * 8 + 2 * q);
            float bo = __ldg(b1p + ni * 8 + 2 * q + 1);
            int ac = acol0 + ni * 4 + q;
            if (r1 < nv)
                g_act[(size_t)(mrowbase + r1) * F_ + ac] =
                    swiglu(acc[mi][ni][0] + be, acc[mi][ni][1] + bo);
            if (r1 + 8 < nv)
                g_act[(size_t)(mrowbase + r1 + 8) * F_ + ac] =
                    swiglu(acc[mi][ni][2] + be, acc[mi][ni][3] + bo);
        }
    }
}

__global__ void __launch_bounds__(256, 2)
k_mlp2(const float* __restrict__ w2, const float* __restrict__ b2) {
    extern __shared__ char smem[];
    int e = blockIdx.z, mtile = blockIdx.y, ntile = blockIdx.x;
    int cnt = g_cnt[e];
    if (mtile * 128 >= cnt) return;
    int off = g_off[e];
    int tid = threadIdx.x, wid = tid >> 5, lane = tid & 31;
    int wm = wid & 3, wn = wid >> 2;
    int grp = lane >> 3, rin = lane & 7;
    uint32_t sb = smem_u32(smem);

    const float* Bb = w2 + ((size_t)e * H_ + (size_t)ntile * 128) * F_;

    int frow = tid >> 3, fc = tid & 7;
    uint32_t fswz = (uint32_t)((fc ^ (frow & 7)) * 16);

    auto issue = [&](int kt) {
        int s = kt - (kt / 3) * 3;
        int k0 = kt * 32;
        uint32_t Ab = sb + SM_STAGE0 + s * STAGE_B;
        uint32_t Bbuf = Ab + 16384;
        #pragma unroll
        for (int i = 0; i < 4; i++) {
            int row = frow + i * 32;
            int m = mtile * 128 + row;
            int mc = min(m, cnt - 1);
            const float* src = g_act + (size_t)(off + mc) * F_ + k0 + fc * 4;
            int sz = (m < cnt) ? 16 : 0;
            CPA16(Ab + row * 128 + fswz, src, sz);
        }
        #pragma unroll
        for (int i = 0; i < 4; i++) {
            int row = frow + i * 32;
            const float* src = Bb + (size_t)row * F_ + k0 + fc * 4;
            CPA16(Bbuf + row * 128 + fswz, src, 16);
        }
        CPA_COMMIT();
    };

    float acc[2][8][4];
    #pragma unroll
    for (int mi = 0; mi < 2; mi++)
        #pragma unroll
        for (int ni = 0; ni < 8; ni++)
            #pragma unroll
            for (int q = 0; q < 4; q++) acc[mi][ni][q] = 0.f;

    issue(0); issue(1);

    uint32_t aOff = (uint32_t)((wm * 32 + (grp & 1) * 8 + rin) * 128);
    uint32_t bOff = (uint32_t)((wn * 64 + (grp >> 1) * 8 + rin) * 128);
    int caH = grp >> 1, cbH = grp & 1;

    for (int kt = 0; kt < 32; kt++) {
        int s = kt - (kt / 3) * 3;
        if (kt < 30) { CPA_WAIT1(); } else { CPA_WAIT0(); }
        __syncthreads();
        if (kt + 2 < 32) issue(kt + 2);

        uint32_t Ab = sb + SM_STAGE0 + s * STAGE_B;
        uint32_t Bbuf = Ab + 16384;
        uint32_t aBase = Ab + aOff;
        uint32_t bBase = Bbuf + bOff;

        #pragma unroll
        for (int ks = 0; ks < 4; ks++) {
            uint32_t a[2][4], b[4][4];
            uint32_t ca = (uint32_t)(((2 * ks + caH) ^ rin) * 16);
            uint32_t cb = (uint32_t)(((2 * ks + cbH) ^ rin) * 16);
            LDMX4(a[0], aBase + ca);
            LDMX4(a[1], aBase + 2048 + ca);
            #pragma unroll
            for (int j = 0; j < 4; j++) LDMX4(b[j], bBase + j * 2048 + cb);
            #pragma unroll
            for (int mi = 0; mi < 2; mi++)
                #pragma unroll
                for (int j = 0; j < 4; j++) {
                    MMA8(acc[mi][2*j],     a[mi], b[j][0], b[j][1]);
                    MMA8(acc[mi][2*j + 1], a[mi], b[j][2], b[j][3]);
                }
        }
    }

    // fused epilogue: (acc + b2) * routing weight -> g_comb
    int nv = min(128, cnt - mtile * 128);
    int q = lane & 3, rr = lane >> 2;
    const float* b2p = b2 + (size_t)e * H_ + ntile * 128 + wn * 64;
    int ocol0 = ntile * 128 + wn * 64;
    int slotbase = off + mtile * 128;
    #pragma unroll
    for (int mi = 0; mi < 2; mi++) {
        int r1 = wm * 32 + mi * 16 + rr;
        float sw1 = (r1 < nv)     ? g_sw[slotbase + r1]     : 0.f;
        float sw2 = (r1 + 8 < nv) ? g_sw[slotbase + r1 + 8] : 0.f;
        #pragma unroll
        for (int ni = 0; ni < 8; ni++) {
            int c0 = ni * 8 + 2 * q;
            float be = __ldg(b2p + c0);
            float bo = __ldg(b2p + c0 + 1);
            if (r1 < nv) {
                float2 v = make_float2((acc[mi][ni][0] + be) * sw1,
                                       (acc[mi][ni][1] + bo) * sw1);
                *(float2*)&g_comb[(size_t)(slotbase + r1) * H_ + ocol0 + c0] = v;
            }
            if (r1 + 8 < nv) {
                float2 v = make_float2((acc[mi][ni][2] + be) * sw2,
                                       (acc[mi][ni][3] + bo) * sw2);
                *(float2*)&g_comb[(size_t)(slotbase + r1 + 8) * H_ + ocol0 + c0] = v;
            }
        }
    }
}

// ---------------- kernel 5: combine + residual ----------------
__global__ void k_combine(const float* __restrict__ x, float* __restrict__ out) {
    int t = blockIdx.x;
    int s0 = g_tslot[t * KK + 0];
    int s1 = g_tslot[t * KK + 1];
    int s2 = g_tslot[t * KK + 2];
    int s3 = g_tslot[t * KK + 3];
    for (int h = threadIdx.x; h < H_; h += 256) {
        out[(size_t)t * H_ + h] = x[(size_t)t * H_ + h]
            + g_comb[(size_t)s0 * H_ + h]
            + g_comb[(size_t)s1 * H_ + h]
            + g_comb[(size_t)s2 * H_ + h]
            + g_comb[(size_t)s3 * H_ + h];
    }
}

// ---------------- launch ----------------
extern "C" void kernel_launch(void* const* d_in, const int* in_sizes, int n_in,
                              void* d_out, int out_size) {
    const float* x  = (const float*)d_in[0];
    const float* ns = (const float*)d_in[1];
    const float* gw = (const float*)d_in[2];
    const float* gb = (const float*)d_in[3];
    const float* w1 = (const float*)d_in[4];
    const float* b1 = (const float*)d_in[5];
    const float* w2 = (const float*)d_in[6];
    const float* b2 = (const float*)d_in[7];
    float* out = (float*)d_out;

    cudaFuncSetAttribute(k_mlp1, cudaFuncAttributeMaxDynamicSharedMemorySize, SMEM_MLP);
    cudaFuncSetAttribute(k_mlp2, cudaFuncAttributeMaxDynamicSharedMemorySize, SMEM_MLP);

    k_norm_gate<<<T_, 256>>>(x, ns, gw, gb);
    k_build<<<1, 1024>>>();
    k_mlp1<<<dim3(16, 8, 32), 256, SMEM_MLP>>>(w1, b1);
    k_mlp2<<<dim3(8, 8, 32), 256, SMEM_MLP>>>(w2, b2);
    k_combine<<<T_, 256>>>(x, out);
}